// round 12
// baseline (speedup 1.0000x reference)
#include <cuda_runtime.h>
#include <cuda_fp16.h>
#include <cstdint>

#define B_SZ 4
#define D_SZ 32
#define N_SZ 4096
#define BM 64                  // m-cols per CTA (2 CTAs/SM)
#define TN 128
#define NTILES (N_SZ / TN)
#define THREADS 256
#define YMQS 68                // ymq stride (u32)
#define Y16S 68                // y16n stride (u32); row stride 272B -> LDSM conflict-free

__device__ float g_ping[B_SZ * D_SZ * N_SZ];
__device__ float g_pong[B_SZ * D_SZ * N_SZ];

// smem u32-word offsets
#define OFF_YMQ 0                           // [16][68] = 1088 (fp16x2 C1*Ym, d-paired)
#define OFF_Y16N 1088                       // 2 x [32][68] = 4352 (fp16x2 yn, n-paired)
#define OFF_SS 8192                         // [4][64] (after zst region)
#define SMEM_WORDS 8448
#define SMEM_BYTES (SMEM_WORDS * 4)         // 33792
// zst aliases words 0..8191 post-loop

static __device__ __forceinline__ uint32_t smem_u32(const void* p) {
    uint32_t a;
    asm("{ .reg .u64 t; cvta.to.shared.u64 t, %1; cvt.u32.u64 %0, t; }" : "=r"(a) : "l"(p));
    return a;
}
static __device__ __forceinline__ float ex2a(float x) {
    float r; asm("ex2.approx.f32 %0, %1;" : "=f"(r) : "f"(x)); return r;
}
static __device__ __forceinline__ uint32_t packh2(float lo, float hi) {
    __half2 h = __floats2half2_rn(lo, hi);
    return *reinterpret_cast<uint32_t*>(&h);
}
static __device__ __forceinline__ void ldsm_x4_t(uint32_t* r, uint32_t addr) {
    asm volatile("ldmatrix.sync.aligned.m8n8.x4.trans.shared.b16 {%0,%1,%2,%3}, [%4];"
        : "=r"(r[0]), "=r"(r[1]), "=r"(r[2]), "=r"(r[3]) : "r"(addr));
}
static __device__ __forceinline__ uint32_t movm(uint32_t a) {
    uint32_t d;
    asm("movmatrix.sync.aligned.m8n8.trans.b16 %0, %1;" : "=r"(d) : "r"(a));
    return d;
}
static __device__ __forceinline__ void mma16h(float* c, const uint32_t* a,
                                              uint32_t b0, uint32_t b1) {
    asm("mma.sync.aligned.m16n8k16.row.col.f32.f16.f16.f32 "
        "{%0,%1,%2,%3},{%4,%5,%6,%7},{%8,%9},{%0,%1,%2,%3};"
        : "+f"(c[0]), "+f"(c[1]), "+f"(c[2]), "+f"(c[3])
        : "r"(a[0]), "r"(a[1]), "r"(a[2]), "r"(a[3]), "r"(b0), "r"(b1));
}

// Mean-shift iteration, all-fp16 tensor path. Kt stays in registers
// (MMA1 C-frag == MMA2 A-frag layout). MMA1's trans-loaded B blocks are
// converted to MMA2's non-trans B-frags via movmatrix (same 8x8 blocks),
// halving LDSM wavefronts. C1=0.1*log2(e) folded into the Ym operand.
__global__ __launch_bounds__(THREADS, 2)
void ms_iter_mma(const float* __restrict__ xin, float* __restrict__ xout, int mode) {
    extern __shared__ float sm[];
    uint32_t* smw  = reinterpret_cast<uint32_t*>(sm);
    uint32_t* ymq  = smw + OFF_YMQ;
    uint32_t* y16n = smw + OFF_Y16N;
    float*    sst  = sm + OFF_SS;

    const float* gin  = (mode == 0) ? xin    : (mode == 1 ? g_ping : g_pong);
    float*       gout = (mode == 0) ? g_ping : (mode == 1 ? g_pong : xout);
    const int b  = blockIdx.y;
    const int m0 = blockIdx.x * BM;
    const float* Y = gin  + b * (D_SZ * N_SZ);
    float*       O = gout + b * (D_SZ * N_SZ);

    const int t    = threadIdx.x;
    const int lane = t & 31;
    const int wid  = t >> 5;
    const int g    = lane >> 2;
    const int k4   = lane & 3;
    const int wm   = wid & 1;
    const int wn   = wid >> 1;
    const int mr   = wm * 32;
    const float C1 = 0.14426950408889634f;   // 0.1 * log2(e)

    // ldmatrix per-lane base address (bytes), MMA1 trans loads:
    // mat = {d-octet lo/hi, n-col half} -> regs (d0-7,n0-7),(d8-15,n0-7),(d0-7,n8-15),(d8-15,n8-15)
    const int mat = lane >> 3, rr = lane & 7;
    const uint32_t y16b = smem_u32(sm) + OFF_Y16N * 4;
    const uint32_t a1base = y16b + (uint32_t)((((mat & 1) * 8 + rr) * Y16S
                                               + 16 * wn + (mat >> 1) * 4) * 4);

    // staging ids: thread covers row sd, 16 pixels at sc
    const int sd = t >> 3;
    const int sc = (t & 7) * 16;

    // ---- stage ymq: [dpair r][m] = pack(C1*Y[2r][m], C1*Y[2r+1][m]) ----
    #pragma unroll
    for (int r2 = 0; r2 < 2; r2++) {
        int v = t + r2 * THREADS;                // 512 items
        int r = v >> 5, mm = (v & 31) * 2;
        float2 x0 = *(const float2*)&Y[(2 * r) * N_SZ + m0 + mm];
        float2 x1 = *(const float2*)&Y[(2 * r + 1) * N_SZ + m0 + mm];
        ymq[r * YMQS + mm]     = packh2(C1 * x0.x, C1 * x1.x);
        ymq[r * YMQS + mm + 1] = packh2(C1 * x0.y, C1 * x1.y);
    }
    // ---- stage y16n buf0: row sd, pixels sc..sc+15 ----
    {
        float4 q0 = *(const float4*)&Y[sd * N_SZ + sc];
        float4 q1 = *(const float4*)&Y[sd * N_SZ + sc + 4];
        float4 q2 = *(const float4*)&Y[sd * N_SZ + sc + 8];
        float4 q3 = *(const float4*)&Y[sd * N_SZ + sc + 12];
        uint32_t* dst = y16n + sd * Y16S + (sc >> 1);
        uint4 u0 = make_uint4(packh2(q0.x, q0.y), packh2(q0.z, q0.w),
                              packh2(q1.x, q1.y), packh2(q1.z, q1.w));
        uint4 u1 = make_uint4(packh2(q2.x, q2.y), packh2(q2.z, q2.w),
                              packh2(q3.x, q3.y), packh2(q3.z, q3.w));
        *(uint4*)&dst[0] = u0;
        *(uint4*)&dst[4] = u1;
    }
    __syncthreads();

    // ---- hoist A1 frags (fp16, pre-scaled by C1): 32 Ym rows, 2 k16 chunks ----
    uint32_t a1h[2][2][4];
    #pragma unroll
    for (int mi = 0; mi < 2; mi++)
        #pragma unroll
        for (int kc = 0; kc < 2; kc++) {
            int row = mr + mi * 16 + g;
            a1h[mi][kc][0] = ymq[(8 * kc + k4) * YMQS + row];
            a1h[mi][kc][1] = ymq[(8 * kc + k4) * YMQS + row + 8];
            a1h[mi][kc][2] = ymq[(8 * kc + 4 + k4) * YMQS + row];
            a1h[mi][kc][3] = ymq[(8 * kc + 4 + k4) * YMQS + row + 8];
        }

    float z[2][4][4];
    #pragma unroll
    for (int i = 0; i < 2; i++)
        #pragma unroll
        for (int j = 0; j < 4; j++)
            #pragma unroll
            for (int q = 0; q < 4; q++) z[i][j][q] = 0.0f;
    float Sp[2][2] = {{0.0f, 0.0f}, {0.0f, 0.0f}};

    for (int nt = 0; nt < NTILES; nt++) {
        const uint32_t bufoff = (uint32_t)(nt & 1) * (32 * Y16S * 4);
        // ---- prefetch next yn tile into regs ----
        float4 pr[4];
        if (nt < NTILES - 1) {
            const int n1 = (nt + 1) * TN;
            pr[0] = *(const float4*)&Y[sd * N_SZ + n1 + sc];
            pr[1] = *(const float4*)&Y[sd * N_SZ + n1 + sc + 4];
            pr[2] = *(const float4*)&Y[sd * N_SZ + n1 + sc + 8];
            pr[3] = *(const float4*)&Y[sd * N_SZ + n1 + sc + 12];
        }

        // ---- per 16-col group: MMA1 -> ex2+pack -> MMA2, Kt in registers ----
        #pragma unroll
        for (int nip = 0; nip < 2; nip++) {
            float c[2][2][4];                    // [ni][mi][q]
            #pragma unroll
            for (int i = 0; i < 2; i++)
                #pragma unroll
                for (int j = 0; j < 2; j++)
                    #pragma unroll
                    for (int q = 0; q < 4; q++) c[i][j][q] = 0.0f;
            uint32_t bq0[4], bq1[4];
            ldsm_x4_t(bq0, a1base + bufoff + (uint32_t)(nip * 32));
            ldsm_x4_t(bq1, a1base + bufoff + (uint32_t)(16 * Y16S * 4 + nip * 32));
            mma16h(c[0][0], a1h[0][0], bq0[0], bq0[1]);
            mma16h(c[0][1], a1h[1][0], bq0[0], bq0[1]);
            mma16h(c[1][0], a1h[0][0], bq0[2], bq0[3]);
            mma16h(c[1][1], a1h[1][0], bq0[2], bq0[3]);
            mma16h(c[0][0], a1h[0][1], bq1[0], bq1[1]);
            mma16h(c[0][1], a1h[1][1], bq1[0], bq1[1]);
            mma16h(c[1][0], a1h[0][1], bq1[2], bq1[3]);
            mma16h(c[1][1], a1h[1][1], bq1[2], bq1[3]);

            // movmatrix: trans frags -> MMA2 non-trans B-frags (same 8x8 blocks);
            // independent of the MMA1 accumulator chain -> issues underneath it.
            uint32_t b2a[4], b2b[4];
            b2a[0] = movm(bq0[0]); b2a[1] = movm(bq0[2]);
            b2a[2] = movm(bq0[1]); b2a[3] = movm(bq0[3]);
            b2b[0] = movm(bq1[0]); b2b[1] = movm(bq1[2]);
            b2b[2] = movm(bq1[1]); b2b[3] = movm(bq1[3]);

            // ex2 + pack: MMA1 C-frags -> MMA2 A-frags in registers
            uint32_t af[2][4];
            #pragma unroll
            for (int mi = 0; mi < 2; mi++) {
                float e00 = ex2a(c[0][mi][0]), e01 = ex2a(c[0][mi][1]);
                float e02 = ex2a(c[0][mi][2]), e03 = ex2a(c[0][mi][3]);
                float e10 = ex2a(c[1][mi][0]), e11 = ex2a(c[1][mi][1]);
                float e12 = ex2a(c[1][mi][2]), e13 = ex2a(c[1][mi][3]);
                Sp[mi][0] += (e00 + e01) + (e10 + e11);   // rows g
                Sp[mi][1] += (e02 + e03) + (e12 + e13);   // rows 8+g
                af[mi][0] = packh2(e00, e01);
                af[mi][1] = packh2(e02, e03);
                af[mi][2] = packh2(e10, e11);
                af[mi][3] = packh2(e12, e13);
            }
            // MMA2: k = these 16 n-cols
            mma16h(z[0][0], af[0], b2a[0], b2a[1]);
            mma16h(z[1][0], af[1], b2a[0], b2a[1]);
            mma16h(z[0][1], af[0], b2a[2], b2a[3]);
            mma16h(z[1][1], af[1], b2a[2], b2a[3]);
            mma16h(z[0][2], af[0], b2b[0], b2b[1]);
            mma16h(z[1][2], af[1], b2b[0], b2b[1]);
            mma16h(z[0][3], af[0], b2b[2], b2b[3]);
            mma16h(z[1][3], af[1], b2b[2], b2b[3]);
        }

        // ---- publish next buffer ----
        if (nt < NTILES - 1) {
            uint32_t* nb = y16n + ((nt + 1) & 1) * (32 * Y16S);
            uint32_t* dst = nb + sd * Y16S + (sc >> 1);
            uint4 u0 = make_uint4(packh2(pr[0].x, pr[0].y), packh2(pr[0].z, pr[0].w),
                                  packh2(pr[1].x, pr[1].y), packh2(pr[1].z, pr[1].w));
            uint4 u1 = make_uint4(packh2(pr[2].x, pr[2].y), packh2(pr[2].z, pr[2].w),
                                  packh2(pr[3].x, pr[3].y), packh2(pr[3].z, pr[3].w));
            *(uint4*)&dst[0] = u0;
            *(uint4*)&dst[4] = u1;
        }
        __syncthreads();
    }

    // ---- S quad-reduce (over k4 lanes) ----
    #pragma unroll
    for (int mi = 0; mi < 2; mi++)
        #pragma unroll
        for (int h = 0; h < 2; h++) {
            Sp[mi][h] += __shfl_xor_sync(0xFFFFFFFFu, Sp[mi][h], 1);
            Sp[mi][h] += __shfl_xor_sync(0xFFFFFFFFu, Sp[mi][h], 2);
        }
    // loop-end __syncthreads() ordered all smem reads -> alias words 0.. as zst

    float* zst = sm;                       // [4 wn][64 m][32 d] = 8192 floats
    if (k4 == 0) {
        #pragma unroll
        for (int mi = 0; mi < 2; mi++) {
            sst[wn * 64 + mr + mi * 16 + g]     = Sp[mi][0];
            sst[wn * 64 + mr + mi * 16 + g + 8] = Sp[mi][1];
        }
    }
    #pragma unroll
    for (int mi = 0; mi < 2; mi++)
        #pragma unroll
        for (int di = 0; di < 4; di++) {
            int row = mr + mi * 16 + g;
            int d   = di * 8 + 2 * k4;
            float2 lo, hi;
            lo.x = z[mi][di][0]; lo.y = z[mi][di][1];
            hi.x = z[mi][di][2]; hi.y = z[mi][di][3];
            *(float2*)&zst[wn * 2048 + row * 32 + d]       = lo;
            *(float2*)&zst[wn * 2048 + (row + 8) * 32 + d] = hi;
        }
    __syncthreads();

    // ---- final: sum 4 wn slices, normalize, blend, store ----
    {
        const int m  = t & 63;
        const int d0 = (t >> 6) * 8;
        float Ssum = sst[m] + sst[64 + m] + sst[128 + m] + sst[192 + m];
        float inv = 0.5f / Ssum;
        #pragma unroll
        for (int dd = 0; dd < 8; dd++) {
            int d = d0 + dd;
            float zz = zst[m * 32 + d] + zst[2048 + m * 32 + d] +
                       zst[4096 + m * 32 + d] + zst[6144 + m * 32 + d];
            O[d * N_SZ + m0 + m] = zz * inv + 0.5f * Y[d * N_SZ + m0 + m];
        }
    }
}

extern "C" void kernel_launch(void* const* d_in, const int* in_sizes, int n_in,
                              void* d_out, int out_size) {
    const float* x = (const float*)d_in[0];
    float* out = (float*)d_out;
    cudaFuncSetAttribute(ms_iter_mma, cudaFuncAttributeMaxDynamicSharedMemorySize,
                         SMEM_BYTES);
    dim3 grid(N_SZ / BM, B_SZ);
    ms_iter_mma<<<grid, THREADS, SMEM_BYTES>>>(x, out, 0);   // x      -> g_ping
    ms_iter_mma<<<grid, THREADS, SMEM_BYTES>>>(x, out, 1);   // g_ping -> g_pong
    ms_iter_mma<<<grid, THREADS, SMEM_BYTES>>>(x, out, 2);   // g_pong -> out
}

// round 13
// speedup vs baseline: 1.1898x; 1.1898x over previous
#include <cuda_runtime.h>
#include <cuda_fp16.h>
#include <cstdint>

#define B_SZ 4
#define D_SZ 32
#define N_SZ 4096
#define NH (N_SZ / 2)
#define BM 64                  // m-cols per CTA (2 CTAs/SM)
#define TN 128
#define NTILES (N_SZ / TN)
#define THREADS 256
#define YMQS 68                // ymq stride (u32)
#define Y16S 68                // y16n stride (u32); row stride 272B -> LDSM conflict-free

// fp16x2 ping/pong scratch (n-paired): scr[b][d][n/2]
__device__ uint32_t g_ping[B_SZ * D_SZ * NH];
__device__ uint32_t g_pong[B_SZ * D_SZ * NH];

// smem u32-word offsets
#define OFF_YMQ 0                           // [16][68] = 1088 (fp16x2 C1*Ym, d-paired)
#define OFF_Y16N 1088                       // 2 x [32][68] = 4352 (fp16x2 yn, n-paired)
#define OFF_SS 8192                         // [4][64] (after zst region)
#define SMEM_WORDS 8448
#define SMEM_BYTES (SMEM_WORDS * 4)         // 33792

static __device__ __forceinline__ uint32_t smem_u32(const void* p) {
    uint32_t a;
    asm("{ .reg .u64 t; cvta.to.shared.u64 t, %1; cvt.u32.u64 %0, t; }" : "=r"(a) : "l"(p));
    return a;
}
static __device__ __forceinline__ float ex2a(float x) {
    float r; asm("ex2.approx.f32 %0, %1;" : "=f"(r) : "f"(x)); return r;
}
static __device__ __forceinline__ uint32_t packh2(float lo, float hi) {
    __half2 h = __floats2half2_rn(lo, hi);
    return *reinterpret_cast<uint32_t*>(&h);
}
static __device__ __forceinline__ float2 unpackh2(uint32_t u) {
    return __half22float2(*reinterpret_cast<__half2*>(&u));
}
static __device__ __forceinline__ void ldsm_x4(uint32_t* r, uint32_t addr) {
    asm volatile("ldmatrix.sync.aligned.m8n8.x4.shared.b16 {%0,%1,%2,%3}, [%4];"
        : "=r"(r[0]), "=r"(r[1]), "=r"(r[2]), "=r"(r[3]) : "r"(addr));
}
static __device__ __forceinline__ void ldsm_x4_t(uint32_t* r, uint32_t addr) {
    asm volatile("ldmatrix.sync.aligned.m8n8.x4.trans.shared.b16 {%0,%1,%2,%3}, [%4];"
        : "=r"(r[0]), "=r"(r[1]), "=r"(r[2]), "=r"(r[3]) : "r"(addr));
}
static __device__ __forceinline__ void mma16h(float* c, const uint32_t* a,
                                              uint32_t b0, uint32_t b1) {
    asm("mma.sync.aligned.m16n8k16.row.col.f32.f16.f16.f32 "
        "{%0,%1,%2,%3},{%4,%5,%6,%7},{%8,%9},{%0,%1,%2,%3};"
        : "+f"(c[0]), "+f"(c[1]), "+f"(c[2]), "+f"(c[3])
        : "r"(a[0]), "r"(a[1]), "r"(a[2]), "r"(a[3]), "r"(b0), "r"(b1));
}

// Mean-shift iteration (R11 structure; movmatrix reverted). IN16/OUT16 select
// fp16x2 scratch vs fp32 harness buffers at the chain ends. For IN16 the tile
// staging is a pure LDG.128->STS.128 copy (halved LDG bytes, no cvt/pack).
template <bool IN16, bool OUT16>
__global__ __launch_bounds__(THREADS, 2)
void ms_iter_mma(const float* __restrict__ xf, const uint32_t* __restrict__ xh,
                 uint32_t* __restrict__ oh, float* __restrict__ of) {
    extern __shared__ float sm[];
    uint32_t* smw  = reinterpret_cast<uint32_t*>(sm);
    uint32_t* ymq  = smw + OFF_YMQ;
    uint32_t* y16n = smw + OFF_Y16N;
    float*    sst  = sm + OFF_SS;

    const int b  = blockIdx.y;
    const int m0 = blockIdx.x * BM;
    const float*    Yf = IN16 ? nullptr : (xf + b * (D_SZ * N_SZ));
    const uint32_t* Yh = IN16 ? (xh + b * (D_SZ * NH)) : nullptr;

    const int t    = threadIdx.x;
    const int lane = t & 31;
    const int wid  = t >> 5;
    const int g    = lane >> 2;
    const int k4   = lane & 3;
    const int wm   = wid & 1;
    const int wn   = wid >> 1;
    const int mr   = wm * 32;
    const float C1 = 0.14426950408889634f;   // 0.1 * log2(e)

    // ldmatrix per-lane base addresses (bytes)
    const int mat = lane >> 3, rr = lane & 7;
    const uint32_t y16b = smem_u32(sm) + OFF_Y16N * 4;
    // MMA1 (.trans): mat = {d-octet lo/hi, n-col half}
    const uint32_t a1base = y16b + (uint32_t)((((mat & 1) * 8 + rr) * Y16S
                                               + 16 * wn + (mat >> 1) * 4) * 4);
    // MMA2 (non-trans): mat = {di-pair half, b0/b1}
    const uint32_t a2base = y16b + (uint32_t)((((mat >> 1) * 8 + rr) * Y16S
                                               + 16 * wn + (mat & 1) * 4) * 4);

    // staging ids: thread covers row sd, 16 pixels at sc
    const int sd = t >> 3;
    const int sc = (t & 7) * 16;

    // ---- stage ymq: [dpair r][m] = pack(C1*Y[2r][m], C1*Y[2r+1][m]) ----
    #pragma unroll
    for (int r2 = 0; r2 < 2; r2++) {
        int v = t + r2 * THREADS;                // 512 items
        int r = v >> 5, mm = (v & 31) * 2;
        float2 fa, fb;
        if (IN16) {
            fa = unpackh2(Yh[(2 * r) * NH + ((m0 + mm) >> 1)]);
            fb = unpackh2(Yh[(2 * r + 1) * NH + ((m0 + mm) >> 1)]);
        } else {
            fa = *(const float2*)&Yf[(2 * r) * N_SZ + m0 + mm];
            fb = *(const float2*)&Yf[(2 * r + 1) * N_SZ + m0 + mm];
        }
        ymq[r * YMQS + mm]     = packh2(C1 * fa.x, C1 * fb.x);
        ymq[r * YMQS + mm + 1] = packh2(C1 * fa.y, C1 * fb.y);
    }
    // ---- stage y16n buf0 ----
    {
        uint4 u0, u1;
        if (IN16) {
            const uint32_t* src = Yh + sd * NH + (sc >> 1);
            u0 = *(const uint4*)&src[0];
            u1 = *(const uint4*)&src[4];
        } else {
            float4 q0 = *(const float4*)&Yf[sd * N_SZ + sc];
            float4 q1 = *(const float4*)&Yf[sd * N_SZ + sc + 4];
            float4 q2 = *(const float4*)&Yf[sd * N_SZ + sc + 8];
            float4 q3 = *(const float4*)&Yf[sd * N_SZ + sc + 12];
            u0 = make_uint4(packh2(q0.x, q0.y), packh2(q0.z, q0.w),
                            packh2(q1.x, q1.y), packh2(q1.z, q1.w));
            u1 = make_uint4(packh2(q2.x, q2.y), packh2(q2.z, q2.w),
                            packh2(q3.x, q3.y), packh2(q3.z, q3.w));
        }
        uint32_t* dst = y16n + sd * Y16S + (sc >> 1);
        *(uint4*)&dst[0] = u0;
        *(uint4*)&dst[4] = u1;
    }
    __syncthreads();

    // ---- hoist A1 frags (fp16, pre-scaled by C1): 32 Ym rows, 2 k16 chunks ----
    uint32_t a1h[2][2][4];
    #pragma unroll
    for (int mi = 0; mi < 2; mi++)
        #pragma unroll
        for (int kc = 0; kc < 2; kc++) {
            int row = mr + mi * 16 + g;
            a1h[mi][kc][0] = ymq[(8 * kc + k4) * YMQS + row];
            a1h[mi][kc][1] = ymq[(8 * kc + k4) * YMQS + row + 8];
            a1h[mi][kc][2] = ymq[(8 * kc + 4 + k4) * YMQS + row];
            a1h[mi][kc][3] = ymq[(8 * kc + 4 + k4) * YMQS + row + 8];
        }

    float z[2][4][4];
    #pragma unroll
    for (int i = 0; i < 2; i++)
        #pragma unroll
        for (int j = 0; j < 4; j++)
            #pragma unroll
            for (int q = 0; q < 4; q++) z[i][j][q] = 0.0f;
    float Sp[2][2] = {{0.0f, 0.0f}, {0.0f, 0.0f}};

    for (int nt = 0; nt < NTILES; nt++) {
        const uint32_t bufoff = (uint32_t)(nt & 1) * (32 * Y16S * 4);
        // ---- prefetch next yn tile into regs ----
        float4 prf[4];
        uint4  prh[2];
        if (nt < NTILES - 1) {
            const int n1 = (nt + 1) * TN;
            if (IN16) {
                const uint32_t* src = Yh + sd * NH + ((n1 + sc) >> 1);
                prh[0] = *(const uint4*)&src[0];
                prh[1] = *(const uint4*)&src[4];
            } else {
                prf[0] = *(const float4*)&Yf[sd * N_SZ + n1 + sc];
                prf[1] = *(const float4*)&Yf[sd * N_SZ + n1 + sc + 4];
                prf[2] = *(const float4*)&Yf[sd * N_SZ + n1 + sc + 8];
                prf[3] = *(const float4*)&Yf[sd * N_SZ + n1 + sc + 12];
            }
        }

        // ---- per 16-col group: MMA1 -> ex2+pack -> MMA2, Kt in registers ----
        #pragma unroll
        for (int nip = 0; nip < 2; nip++) {
            float c[2][2][4];                    // [ni][mi][q]
            #pragma unroll
            for (int i = 0; i < 2; i++)
                #pragma unroll
                for (int j = 0; j < 2; j++)
                    #pragma unroll
                    for (int q = 0; q < 4; q++) c[i][j][q] = 0.0f;
            uint32_t bq0[4], bq1[4];
            ldsm_x4_t(bq0, a1base + bufoff + (uint32_t)(nip * 32));
            ldsm_x4_t(bq1, a1base + bufoff + (uint32_t)(16 * Y16S * 4 + nip * 32));
            mma16h(c[0][0], a1h[0][0], bq0[0], bq0[1]);
            mma16h(c[0][1], a1h[1][0], bq0[0], bq0[1]);
            mma16h(c[1][0], a1h[0][0], bq0[2], bq0[3]);
            mma16h(c[1][1], a1h[1][0], bq0[2], bq0[3]);
            mma16h(c[0][0], a1h[0][1], bq1[0], bq1[1]);
            mma16h(c[0][1], a1h[1][1], bq1[0], bq1[1]);
            mma16h(c[1][0], a1h[0][1], bq1[2], bq1[3]);
            mma16h(c[1][1], a1h[1][1], bq1[2], bq1[3]);

            // ex2 + pack: MMA1 C-frags -> MMA2 A-frags in registers
            uint32_t af[2][4];
            #pragma unroll
            for (int mi = 0; mi < 2; mi++) {
                float e00 = ex2a(c[0][mi][0]), e01 = ex2a(c[0][mi][1]);
                float e02 = ex2a(c[0][mi][2]), e03 = ex2a(c[0][mi][3]);
                float e10 = ex2a(c[1][mi][0]), e11 = ex2a(c[1][mi][1]);
                float e12 = ex2a(c[1][mi][2]), e13 = ex2a(c[1][mi][3]);
                Sp[mi][0] += (e00 + e01) + (e10 + e11);   // rows g
                Sp[mi][1] += (e02 + e03) + (e12 + e13);   // rows 8+g
                af[mi][0] = packh2(e00, e01);
                af[mi][1] = packh2(e02, e03);
                af[mi][2] = packh2(e10, e11);
                af[mi][3] = packh2(e12, e13);
            }
            // MMA2: k = these 16 n-cols; B-frags via non-trans ldmatrix
            uint32_t b2a[4], b2b[4];
            ldsm_x4(b2a, a2base + bufoff + (uint32_t)(nip * 32));
            ldsm_x4(b2b, a2base + bufoff + (uint32_t)(16 * Y16S * 4 + nip * 32));
            mma16h(z[0][0], af[0], b2a[0], b2a[1]);
            mma16h(z[1][0], af[1], b2a[0], b2a[1]);
            mma16h(z[0][1], af[0], b2a[2], b2a[3]);
            mma16h(z[1][1], af[1], b2a[2], b2a[3]);
            mma16h(z[0][2], af[0], b2b[0], b2b[1]);
            mma16h(z[1][2], af[1], b2b[0], b2b[1]);
            mma16h(z[0][3], af[0], b2b[2], b2b[3]);
            mma16h(z[1][3], af[1], b2b[2], b2b[3]);
        }

        // ---- publish next buffer ----
        if (nt < NTILES - 1) {
            uint32_t* nb  = y16n + ((nt + 1) & 1) * (32 * Y16S);
            uint32_t* dst = nb + sd * Y16S + (sc >> 1);
            uint4 u0, u1;
            if (IN16) {
                u0 = prh[0];
                u1 = prh[1];
            } else {
                u0 = make_uint4(packh2(prf[0].x, prf[0].y), packh2(prf[0].z, prf[0].w),
                                packh2(prf[1].x, prf[1].y), packh2(prf[1].z, prf[1].w));
                u1 = make_uint4(packh2(prf[2].x, prf[2].y), packh2(prf[2].z, prf[2].w),
                                packh2(prf[3].x, prf[3].y), packh2(prf[3].z, prf[3].w));
            }
            *(uint4*)&dst[0] = u0;
            *(uint4*)&dst[4] = u1;
        }
        __syncthreads();
    }

    // ---- S quad-reduce (over k4 lanes) ----
    #pragma unroll
    for (int mi = 0; mi < 2; mi++)
        #pragma unroll
        for (int h = 0; h < 2; h++) {
            Sp[mi][h] += __shfl_xor_sync(0xFFFFFFFFu, Sp[mi][h], 1);
            Sp[mi][h] += __shfl_xor_sync(0xFFFFFFFFu, Sp[mi][h], 2);
        }
    // loop-end __syncthreads() ordered all smem reads -> alias words 0.. as zst

    float* zst = sm;                       // [4 wn][64 m][32 d] = 8192 floats
    if (k4 == 0) {
        #pragma unroll
        for (int mi = 0; mi < 2; mi++) {
            sst[wn * 64 + mr + mi * 16 + g]     = Sp[mi][0];
            sst[wn * 64 + mr + mi * 16 + g + 8] = Sp[mi][1];
        }
    }
    #pragma unroll
    for (int mi = 0; mi < 2; mi++)
        #pragma unroll
        for (int di = 0; di < 4; di++) {
            int row = mr + mi * 16 + g;
            int d   = di * 8 + 2 * k4;
            float2 lo, hi;
            lo.x = z[mi][di][0]; lo.y = z[mi][di][1];
            hi.x = z[mi][di][2]; hi.y = z[mi][di][3];
            *(float2*)&zst[wn * 2048 + row * 32 + d]       = lo;
            *(float2*)&zst[wn * 2048 + (row + 8) * 32 + d] = hi;
        }
    __syncthreads();

    // ---- final: sum 4 wn slices, normalize, blend, store (m-pair per thread) ----
    {
        const int mp = t & 31;             // m-pair id: local m = 2mp, 2mp+1
        const int d0 = (t >> 5) * 4;
        const int ml = 2 * mp;
        float S0 = sst[ml] + sst[64 + ml] + sst[128 + ml] + sst[192 + ml];
        float S1 = sst[ml + 1] + sst[64 + ml + 1] + sst[128 + ml + 1] + sst[192 + ml + 1];
        float inv0 = 0.5f / S0, inv1 = 0.5f / S1;
        #pragma unroll
        for (int dd = 0; dd < 4; dd++) {
            int d = d0 + dd;
            float z0 = zst[ml * 32 + d] + zst[2048 + ml * 32 + d] +
                       zst[4096 + ml * 32 + d] + zst[6144 + ml * 32 + d];
            float z1 = zst[(ml + 1) * 32 + d] + zst[2048 + (ml + 1) * 32 + d] +
                       zst[4096 + (ml + 1) * 32 + d] + zst[6144 + (ml + 1) * 32 + d];
            float y0, y1;
            if (IN16) {
                float2 f = unpackh2(Yh[d * NH + ((m0 + ml) >> 1)]);
                y0 = f.x; y1 = f.y;
            } else {
                y0 = Yf[d * N_SZ + m0 + ml];
                y1 = Yf[d * N_SZ + m0 + ml + 1];
            }
            float o0 = z0 * inv0 + 0.5f * y0;
            float o1 = z1 * inv1 + 0.5f * y1;
            if (OUT16) {
                oh[b * (D_SZ * NH) + d * NH + ((m0 + ml) >> 1)] = packh2(o0, o1);
            } else {
                float* po = of + b * (D_SZ * N_SZ) + d * N_SZ + m0 + ml;
                po[0] = o0;
                po[1] = o1;
            }
        }
    }
}

extern "C" void kernel_launch(void* const* d_in, const int* in_sizes, int n_in,
                              void* d_out, int out_size) {
    const float* x = (const float*)d_in[0];
    float* out = (float*)d_out;
    uint32_t *ping, *pong;
    cudaGetSymbolAddress((void**)&ping, g_ping);
    cudaGetSymbolAddress((void**)&pong, g_pong);
    cudaFuncSetAttribute(ms_iter_mma<false, true>,
                         cudaFuncAttributeMaxDynamicSharedMemorySize, SMEM_BYTES);
    cudaFuncSetAttribute(ms_iter_mma<true, true>,
                         cudaFuncAttributeMaxDynamicSharedMemorySize, SMEM_BYTES);
    cudaFuncSetAttribute(ms_iter_mma<true, false>,
                         cudaFuncAttributeMaxDynamicSharedMemorySize, SMEM_BYTES);
    dim3 grid(N_SZ / BM, B_SZ);
    ms_iter_mma<false, true><<<grid, THREADS, SMEM_BYTES>>>(x, nullptr, ping, nullptr);
    ms_iter_mma<true, true><<<grid, THREADS, SMEM_BYTES>>>(nullptr, ping, pong, nullptr);
    ms_iter_mma<true, false><<<grid, THREADS, SMEM_BYTES>>>(nullptr, pong, nullptr, out);
}

// round 14
// speedup vs baseline: 1.2309x; 1.0345x over previous
#include <cuda_runtime.h>
#include <cuda_fp16.h>
#include <cstdint>

#define B_SZ 4
#define D_SZ 32
#define N_SZ 4096
#define NH (N_SZ / 2)
#define BM 64                  // m-cols per CTA (2 CTAs/SM)
#define TN 128
#define NTILES (N_SZ / TN)
#define THREADS 256
#define YMQS 68                // ymq stride (u32)
#define Y16S 68                // y16n stride (u32); row stride 272B -> LDSM conflict-free

// fp16x2 buffers (n-paired): [b][d][n/2]
__device__ uint32_t g_x16[B_SZ * D_SZ * NH];
__device__ uint32_t g_ping[B_SZ * D_SZ * NH];
__device__ uint32_t g_pong[B_SZ * D_SZ * NH];

// smem u32-word offsets
#define OFF_YMQ 0                           // [16][68] = 1088 (fp16x2 C1*Ym, d-paired)
#define OFF_Y16N 1088                       // 2 x [32][68] = 4352 (fp16x2 yn, n-paired)
#define OFF_SS 8192                         // [4][64] (after zst region)
#define SMEM_WORDS 8448
#define SMEM_BYTES (SMEM_WORDS * 4)         // 33792

static __device__ __forceinline__ uint32_t smem_u32(const void* p) {
    uint32_t a;
    asm("{ .reg .u64 t; cvta.to.shared.u64 t, %1; cvt.u32.u64 %0, t; }" : "=r"(a) : "l"(p));
    return a;
}
static __device__ __forceinline__ uint32_t ex2h2(uint32_t x) {
    uint32_t r; asm("ex2.approx.f16x2 %0, %1;" : "=r"(r) : "r"(x)); return r;
}
static __device__ __forceinline__ uint32_t packh2(float lo, float hi) {
    __half2 h = __floats2half2_rn(lo, hi);
    return *reinterpret_cast<uint32_t*>(&h);
}
static __device__ __forceinline__ float2 unpackh2(uint32_t u) {
    return __half22float2(*reinterpret_cast<__half2*>(&u));
}
static __device__ __forceinline__ void ldsm_x4(uint32_t* r, uint32_t addr) {
    asm volatile("ldmatrix.sync.aligned.m8n8.x4.shared.b16 {%0,%1,%2,%3}, [%4];"
        : "=r"(r[0]), "=r"(r[1]), "=r"(r[2]), "=r"(r[3]) : "r"(addr));
}
static __device__ __forceinline__ void ldsm_x4_t(uint32_t* r, uint32_t addr) {
    asm volatile("ldmatrix.sync.aligned.m8n8.x4.trans.shared.b16 {%0,%1,%2,%3}, [%4];"
        : "=r"(r[0]), "=r"(r[1]), "=r"(r[2]), "=r"(r[3]) : "r"(addr));
}
static __device__ __forceinline__ void mma16h(float* c, const uint32_t* a,
                                              uint32_t b0, uint32_t b1) {
    asm("mma.sync.aligned.m16n8k16.row.col.f32.f16.f16.f32 "
        "{%0,%1,%2,%3},{%4,%5,%6,%7},{%8,%9},{%0,%1,%2,%3};"
        : "+f"(c[0]), "+f"(c[1]), "+f"(c[2]), "+f"(c[3])
        : "r"(a[0]), "r"(a[1]), "r"(a[2]), "r"(a[3]), "r"(b0), "r"(b1));
}

// fp32 -> fp16x2 pre-convert (whole input, once)
__global__ __launch_bounds__(256) void cvt16(const float* __restrict__ x,
                                             uint32_t* __restrict__ o) {
    int i = (blockIdx.x * 256 + threadIdx.x) * 4;   // u32 quad index
    float4 a = *(const float4*)&x[2 * i];
    float4 b = *(const float4*)&x[2 * i + 4];
    uint4 u = make_uint4(packh2(a.x, a.y), packh2(a.z, a.w),
                         packh2(b.x, b.y), packh2(b.z, b.w));
    *(uint4*)&o[i] = u;
}

// Mean-shift iteration, all-fp16 chain. exp via packed ex2.approx.f16x2 on the
// fp32 accumulators (C1 folded into Ym) producing the MMA2 A-frag word directly.
template <bool OUT16>
__global__ __launch_bounds__(THREADS, 2)
void ms_iter_mma(const uint32_t* __restrict__ xh, uint32_t* __restrict__ oh,
                 float* __restrict__ of) {
    extern __shared__ float sm[];
    uint32_t* smw  = reinterpret_cast<uint32_t*>(sm);
    uint32_t* ymq  = smw + OFF_YMQ;
    uint32_t* y16n = smw + OFF_Y16N;
    float*    sst  = sm + OFF_SS;

    const int b  = blockIdx.y;
    const int m0 = blockIdx.x * BM;
    const uint32_t* Yh = xh + b * (D_SZ * NH);

    const int t    = threadIdx.x;
    const int lane = t & 31;
    const int wid  = t >> 5;
    const int g    = lane >> 2;
    const int k4   = lane & 3;
    const int wm   = wid & 1;
    const int wn   = wid >> 1;
    const int mr   = wm * 32;
    const float C1 = 0.14426950408889634f;   // 0.1 * log2(e)

    // ldmatrix per-lane base addresses (bytes)
    const int mat = lane >> 3, rr = lane & 7;
    const uint32_t y16b = smem_u32(sm) + OFF_Y16N * 4;
    // MMA1 (.trans): mat = {d-octet lo/hi, n-col half}
    const uint32_t a1base = y16b + (uint32_t)((((mat & 1) * 8 + rr) * Y16S
                                               + 16 * wn + (mat >> 1) * 4) * 4);
    // MMA2 (non-trans): mat = {di-pair half, b0/b1}
    const uint32_t a2base = y16b + (uint32_t)((((mat >> 1) * 8 + rr) * Y16S
                                               + 16 * wn + (mat & 1) * 4) * 4);

    // staging ids: thread covers row sd, 16 pixels at sc
    const int sd = t >> 3;
    const int sc = (t & 7) * 16;

    // ---- stage ymq: [dpair r][m] = pack(C1*Y[2r][m], C1*Y[2r+1][m]) ----
    #pragma unroll
    for (int r2 = 0; r2 < 2; r2++) {
        int v = t + r2 * THREADS;                // 512 items
        int r = v >> 5, mm = (v & 31) * 2;
        float2 fa = unpackh2(Yh[(2 * r) * NH + ((m0 + mm) >> 1)]);
        float2 fb = unpackh2(Yh[(2 * r + 1) * NH + ((m0 + mm) >> 1)]);
        ymq[r * YMQS + mm]     = packh2(C1 * fa.x, C1 * fb.x);
        ymq[r * YMQS + mm + 1] = packh2(C1 * fa.y, C1 * fb.y);
    }
    // ---- stage y16n buf0 (pure copy) ----
    {
        const uint32_t* src = Yh + sd * NH + (sc >> 1);
        uint32_t* dst = y16n + sd * Y16S + (sc >> 1);
        *(uint4*)&dst[0] = *(const uint4*)&src[0];
        *(uint4*)&dst[4] = *(const uint4*)&src[4];
    }
    __syncthreads();

    // ---- hoist A1 frags (fp16, pre-scaled by C1): 32 Ym rows, 2 k16 chunks ----
    uint32_t a1h[2][2][4];
    #pragma unroll
    for (int mi = 0; mi < 2; mi++)
        #pragma unroll
        for (int kc = 0; kc < 2; kc++) {
            int row = mr + mi * 16 + g;
            a1h[mi][kc][0] = ymq[(8 * kc + k4) * YMQS + row];
            a1h[mi][kc][1] = ymq[(8 * kc + k4) * YMQS + row + 8];
            a1h[mi][kc][2] = ymq[(8 * kc + 4 + k4) * YMQS + row];
            a1h[mi][kc][3] = ymq[(8 * kc + 4 + k4) * YMQS + row + 8];
        }

    float z[2][4][4];
    #pragma unroll
    for (int i = 0; i < 2; i++)
        #pragma unroll
        for (int j = 0; j < 4; j++)
            #pragma unroll
            for (int q = 0; q < 4; q++) z[i][j][q] = 0.0f;
    float Sp[2][2] = {{0.0f, 0.0f}, {0.0f, 0.0f}};

    for (int nt = 0; nt < NTILES; nt++) {
        const uint32_t bufoff = (uint32_t)(nt & 1) * (32 * Y16S * 4);
        // ---- prefetch next yn tile into regs ----
        uint4 prh[2];
        if (nt < NTILES - 1) {
            const uint32_t* src = Yh + sd * NH + (((nt + 1) * TN + sc) >> 1);
            prh[0] = *(const uint4*)&src[0];
            prh[1] = *(const uint4*)&src[4];
        }

        // ---- per 16-col group: MMA1 -> h2-ex2 -> MMA2, Kt in registers ----
        #pragma unroll
        for (int nip = 0; nip < 2; nip++) {
            float c[2][2][4];                    // [ni][mi][q]
            #pragma unroll
            for (int i = 0; i < 2; i++)
                #pragma unroll
                for (int j = 0; j < 2; j++)
                    #pragma unroll
                    for (int q = 0; q < 4; q++) c[i][j][q] = 0.0f;
            uint32_t bq0[4], bq1[4];
            ldsm_x4_t(bq0, a1base + bufoff + (uint32_t)(nip * 32));
            ldsm_x4_t(bq1, a1base + bufoff + (uint32_t)(16 * Y16S * 4 + nip * 32));
            mma16h(c[0][0], a1h[0][0], bq0[0], bq0[1]);
            mma16h(c[0][1], a1h[1][0], bq0[0], bq0[1]);
            mma16h(c[1][0], a1h[0][0], bq0[2], bq0[3]);
            mma16h(c[1][1], a1h[1][0], bq0[2], bq0[3]);
            mma16h(c[0][0], a1h[0][1], bq1[0], bq1[1]);
            mma16h(c[0][1], a1h[1][1], bq1[0], bq1[1]);
            mma16h(c[1][0], a1h[0][1], bq1[2], bq1[3]);
            mma16h(c[1][1], a1h[1][1], bq1[2], bq1[3]);

            // packed exp: pack fp32 accums -> f16x2 -> ex2.approx.f16x2 = A-frag
            uint32_t af[2][4];
            #pragma unroll
            for (int mi = 0; mi < 2; mi++) {
                af[mi][0] = ex2h2(packh2(c[0][mi][0], c[0][mi][1]));   // rows g,   cols 0-7
                af[mi][1] = ex2h2(packh2(c[0][mi][2], c[0][mi][3]));   // rows 8+g, cols 0-7
                af[mi][2] = ex2h2(packh2(c[1][mi][0], c[1][mi][1]));   // rows g,   cols 8-15
                af[mi][3] = ex2h2(packh2(c[1][mi][2], c[1][mi][3]));   // rows 8+g, cols 8-15
                float2 f0 = unpackh2(af[mi][0]);
                float2 f1 = unpackh2(af[mi][1]);
                float2 f2 = unpackh2(af[mi][2]);
                float2 f3 = unpackh2(af[mi][3]);
                Sp[mi][0] += (f0.x + f0.y) + (f2.x + f2.y);   // rows g
                Sp[mi][1] += (f1.x + f1.y) + (f3.x + f3.y);   // rows 8+g
            }
            // MMA2: k = these 16 n-cols; B-frags via non-trans ldmatrix
            uint32_t b2a[4], b2b[4];
            ldsm_x4(b2a, a2base + bufoff + (uint32_t)(nip * 32));
            ldsm_x4(b2b, a2base + bufoff + (uint32_t)(16 * Y16S * 4 + nip * 32));
            mma16h(z[0][0], af[0], b2a[0], b2a[1]);
            mma16h(z[1][0], af[1], b2a[0], b2a[1]);
            mma16h(z[0][1], af[0], b2a[2], b2a[3]);
            mma16h(z[1][1], af[1], b2a[2], b2a[3]);
            mma16h(z[0][2], af[0], b2b[0], b2b[1]);
            mma16h(z[1][2], af[1], b2b[0], b2b[1]);
            mma16h(z[0][3], af[0], b2b[2], b2b[3]);
            mma16h(z[1][3], af[1], b2b[2], b2b[3]);
        }

        // ---- publish next buffer ----
        if (nt < NTILES - 1) {
            uint32_t* dst = y16n + ((nt + 1) & 1) * (32 * Y16S) + sd * Y16S + (sc >> 1);
            *(uint4*)&dst[0] = prh[0];
            *(uint4*)&dst[4] = prh[1];
        }
        __syncthreads();
    }

    // ---- S quad-reduce (over k4 lanes) ----
    #pragma unroll
    for (int mi = 0; mi < 2; mi++)
        #pragma unroll
        for (int h = 0; h < 2; h++) {
            Sp[mi][h] += __shfl_xor_sync(0xFFFFFFFFu, Sp[mi][h], 1);
            Sp[mi][h] += __shfl_xor_sync(0xFFFFFFFFu, Sp[mi][h], 2);
        }
    // loop-end __syncthreads() ordered all smem reads -> alias words 0.. as zst

    float* zst = sm;                       // [4 wn][64 m][32 d] = 8192 floats
    if (k4 == 0) {
        #pragma unroll
        for (int mi = 0; mi < 2; mi++) {
            sst[wn * 64 + mr + mi * 16 + g]     = Sp[mi][0];
            sst[wn * 64 + mr + mi * 16 + g + 8] = Sp[mi][1];
        }
    }
    #pragma unroll
    for (int mi = 0; mi < 2; mi++)
        #pragma unroll
        for (int di = 0; di < 4; di++) {
            int row = mr + mi * 16 + g;
            int d   = di * 8 + 2 * k4;
            float2 lo, hi;
            lo.x = z[mi][di][0]; lo.y = z[mi][di][1];
            hi.x = z[mi][di][2]; hi.y = z[mi][di][3];
            *(float2*)&zst[wn * 2048 + row * 32 + d]       = lo;
            *(float2*)&zst[wn * 2048 + (row + 8) * 32 + d] = hi;
        }
    __syncthreads();

    // ---- final: sum 4 wn slices, normalize, blend, store (m-pair per thread) ----
    {
        const int mp = t & 31;             // m-pair id: local m = 2mp, 2mp+1
        const int d0 = (t >> 5) * 4;
        const int ml = 2 * mp;
        float S0 = sst[ml] + sst[64 + ml] + sst[128 + ml] + sst[192 + ml];
        float S1 = sst[ml + 1] + sst[64 + ml + 1] + sst[128 + ml + 1] + sst[192 + ml + 1];
        float inv0 = 0.5f / S0, inv1 = 0.5f / S1;
        #pragma unroll
        for (int dd = 0; dd < 4; dd++) {
            int d = d0 + dd;
            float z0 = zst[ml * 32 + d] + zst[2048 + ml * 32 + d] +
                       zst[4096 + ml * 32 + d] + zst[6144 + ml * 32 + d];
            float z1 = zst[(ml + 1) * 32 + d] + zst[2048 + (ml + 1) * 32 + d] +
                       zst[4096 + (ml + 1) * 32 + d] + zst[6144 + (ml + 1) * 32 + d];
            float2 f = unpackh2(Yh[d * NH + ((m0 + ml) >> 1)]);
            float o0 = z0 * inv0 + 0.5f * f.x;
            float o1 = z1 * inv1 + 0.5f * f.y;
            if (OUT16) {
                oh[b * (D_SZ * NH) + d * NH + ((m0 + ml) >> 1)] = packh2(o0, o1);
            } else {
                float* po = of + b * (D_SZ * N_SZ) + d * N_SZ + m0 + ml;
                po[0] = o0;
                po[1] = o1;
            }
        }
    }
}

extern "C" void kernel_launch(void* const* d_in, const int* in_sizes, int n_in,
                              void* d_out, int out_size) {
    const float* x = (const float*)d_in[0];
    float* out = (float*)d_out;
    uint32_t *x16, *ping, *pong;
    cudaGetSymbolAddress((void**)&x16, g_x16);
    cudaGetSymbolAddress((void**)&ping, g_ping);
    cudaGetSymbolAddress((void**)&pong, g_pong);
    cudaFuncSetAttribute(ms_iter_mma<true>,
                         cudaFuncAttributeMaxDynamicSharedMemorySize, SMEM_BYTES);
    cudaFuncSetAttribute(ms_iter_mma<false>,
                         cudaFuncAttributeMaxDynamicSharedMemorySize, SMEM_BYTES);
    dim3 grid(N_SZ / BM, B_SZ);
    cvt16<<<B_SZ * D_SZ * NH / (256 * 4), 256>>>(x, x16);        // x -> fp16
    ms_iter_mma<true><<<grid, THREADS, SMEM_BYTES>>>(x16, ping, nullptr);
    ms_iter_mma<true><<<grid, THREADS, SMEM_BYTES>>>(ping, pong, nullptr);
    ms_iter_mma<false><<<grid, THREADS, SMEM_BYTES>>>(pong, nullptr, out);
}

// round 15
// speedup vs baseline: 1.3328x; 1.0828x over previous
#include <cuda_runtime.h>
#include <cuda_fp16.h>
#include <cstdint>

#define B_SZ 4
#define D_SZ 32
#define N_SZ 4096
#define NH (N_SZ / 2)
#define BM 64                  // m-cols per CTA (2 CTAs/SM)
#define TN 128
#define NTILES (N_SZ / TN)
#define THREADS 256
#define YMQS 68                // ymq stride (u32)
#define Y16S 68                // y16n stride (u32); row stride 272B -> LDSM conflict-free
#define H2_ONE 0x3C003C00u     // fp16x2 (1.0, 1.0)

// fp16x2 buffers (n-paired): [b][d][n/2]
__device__ uint32_t g_x16[B_SZ * D_SZ * NH];
__device__ uint32_t g_ping[B_SZ * D_SZ * NH];
__device__ uint32_t g_pong[B_SZ * D_SZ * NH];

// smem u32-word offsets
#define OFF_YMQ 0                           // [16][68] = 1088 (fp16x2 C1*Ym, d-paired)
#define OFF_Y16N 1088                       // 2 x [32][68] = 4352 (fp16x2 yn, n-paired)
#define OFF_SS 8192                         // [4][64] (after zst region)
#define SMEM_WORDS 8448
#define SMEM_BYTES (SMEM_WORDS * 4)         // 33792

static __device__ __forceinline__ uint32_t smem_u32(const void* p) {
    uint32_t a;
    asm("{ .reg .u64 t; cvta.to.shared.u64 t, %1; cvt.u32.u64 %0, t; }" : "=r"(a) : "l"(p));
    return a;
}
static __device__ __forceinline__ uint32_t ex2h2(uint32_t x) {
    uint32_t r; asm("ex2.approx.f16x2 %0, %1;" : "=r"(r) : "r"(x)); return r;
}
static __device__ __forceinline__ uint32_t packh2(float lo, float hi) {
    __half2 h = __floats2half2_rn(lo, hi);
    return *reinterpret_cast<uint32_t*>(&h);
}
static __device__ __forceinline__ float2 unpackh2(uint32_t u) {
    return __half22float2(*reinterpret_cast<__half2*>(&u));
}
static __device__ __forceinline__ void ldsm_x4(uint32_t* r, uint32_t addr) {
    asm volatile("ldmatrix.sync.aligned.m8n8.x4.shared.b16 {%0,%1,%2,%3}, [%4];"
        : "=r"(r[0]), "=r"(r[1]), "=r"(r[2]), "=r"(r[3]) : "r"(addr));
}
static __device__ __forceinline__ void ldsm_x4_t(uint32_t* r, uint32_t addr) {
    asm volatile("ldmatrix.sync.aligned.m8n8.x4.trans.shared.b16 {%0,%1,%2,%3}, [%4];"
        : "=r"(r[0]), "=r"(r[1]), "=r"(r[2]), "=r"(r[3]) : "r"(addr));
}
static __device__ __forceinline__ void mma16h(float* c, const uint32_t* a,
                                              uint32_t b0, uint32_t b1) {
    asm("mma.sync.aligned.m16n8k16.row.col.f32.f16.f16.f32 "
        "{%0,%1,%2,%3},{%4,%5,%6,%7},{%8,%9},{%0,%1,%2,%3};"
        : "+f"(c[0]), "+f"(c[1]), "+f"(c[2]), "+f"(c[3])
        : "r"(a[0]), "r"(a[1]), "r"(a[2]), "r"(a[3]), "r"(b0), "r"(b1));
}

// fp32 -> fp16x2 pre-convert (whole input, once)
__global__ __launch_bounds__(256) void cvt16(const float* __restrict__ x,
                                             uint32_t* __restrict__ o) {
    int i = (blockIdx.x * 256 + threadIdx.x) * 4;   // u32 quad index
    float4 a = *(const float4*)&x[2 * i];
    float4 b = *(const float4*)&x[2 * i + 4];
    uint4 u = make_uint4(packh2(a.x, a.y), packh2(a.z, a.w),
                         packh2(b.x, b.y), packh2(b.z, b.w));
    *(uint4*)&o[i] = u;
}

// Mean-shift iteration, all-fp16 chain. exp via ex2.approx.f16x2 producing the
// MMA2 A-frag word directly. S is computed ON THE TENSOR PIPE: a 5th MMA2
// chunk with constant-ones B accumulates S[m] in fp32 exactly (z[.][4]).
template <bool OUT16>
__global__ __launch_bounds__(THREADS, 2)
void ms_iter_mma(const uint32_t* __restrict__ xh, uint32_t* __restrict__ oh,
                 float* __restrict__ of) {
    extern __shared__ float sm[];
    uint32_t* smw  = reinterpret_cast<uint32_t*>(sm);
    uint32_t* ymq  = smw + OFF_YMQ;
    uint32_t* y16n = smw + OFF_Y16N;
    float*    sst  = sm + OFF_SS;

    const int b  = blockIdx.y;
    const int m0 = blockIdx.x * BM;
    const uint32_t* Yh = xh + b * (D_SZ * NH);

    const int t    = threadIdx.x;
    const int lane = t & 31;
    const int wid  = t >> 5;
    const int g    = lane >> 2;
    const int k4   = lane & 3;
    const int wm   = wid & 1;
    const int wn   = wid >> 1;
    const int mr   = wm * 32;
    const float C1 = 0.14426950408889634f;   // 0.1 * log2(e)

    // ldmatrix per-lane base addresses (bytes)
    const int mat = lane >> 3, rr = lane & 7;
    const uint32_t y16b = smem_u32(sm) + OFF_Y16N * 4;
    // MMA1 (.trans): mat = {d-octet lo/hi, n-col half}
    const uint32_t a1base = y16b + (uint32_t)((((mat & 1) * 8 + rr) * Y16S
                                               + 16 * wn + (mat >> 1) * 4) * 4);
    // MMA2 (non-trans): mat = {di-pair half, b0/b1}
    const uint32_t a2base = y16b + (uint32_t)((((mat >> 1) * 8 + rr) * Y16S
                                               + 16 * wn + (mat & 1) * 4) * 4);

    // staging ids: thread covers row sd, 16 pixels at sc
    const int sd = t >> 3;
    const int sc = (t & 7) * 16;

    // ---- stage ymq: [dpair r][m] = pack(C1*Y[2r][m], C1*Y[2r+1][m]) ----
    #pragma unroll
    for (int r2 = 0; r2 < 2; r2++) {
        int v = t + r2 * THREADS;                // 512 items
        int r = v >> 5, mm = (v & 31) * 2;
        float2 fa = unpackh2(Yh[(2 * r) * NH + ((m0 + mm) >> 1)]);
        float2 fb = unpackh2(Yh[(2 * r + 1) * NH + ((m0 + mm) >> 1)]);
        ymq[r * YMQS + mm]     = packh2(C1 * fa.x, C1 * fb.x);
        ymq[r * YMQS + mm + 1] = packh2(C1 * fa.y, C1 * fb.y);
    }
    // ---- stage y16n buf0 (pure copy) ----
    {
        const uint32_t* src = Yh + sd * NH + (sc >> 1);
        uint32_t* dst = y16n + sd * Y16S + (sc >> 1);
        *(uint4*)&dst[0] = *(const uint4*)&src[0];
        *(uint4*)&dst[4] = *(const uint4*)&src[4];
    }
    __syncthreads();

    // ---- hoist A1 frags (fp16, pre-scaled by C1): 32 Ym rows, 2 k16 chunks ----
    uint32_t a1h[2][2][4];
    #pragma unroll
    for (int mi = 0; mi < 2; mi++)
        #pragma unroll
        for (int kc = 0; kc < 2; kc++) {
            int row = mr + mi * 16 + g;
            a1h[mi][kc][0] = ymq[(8 * kc + k4) * YMQS + row];
            a1h[mi][kc][1] = ymq[(8 * kc + k4) * YMQS + row + 8];
            a1h[mi][kc][2] = ymq[(8 * kc + 4 + k4) * YMQS + row];
            a1h[mi][kc][3] = ymq[(8 * kc + 4 + k4) * YMQS + row + 8];
        }

    // z[mi][0..3] = Z data chunks; z[mi][4] = S (ones-B MMA)
    float z[2][5][4];
    #pragma unroll
    for (int i = 0; i < 2; i++)
        #pragma unroll
        for (int j = 0; j < 5; j++)
            #pragma unroll
            for (int q = 0; q < 4; q++) z[i][j][q] = 0.0f;

    for (int nt = 0; nt < NTILES; nt++) {
        const uint32_t bufoff = (uint32_t)(nt & 1) * (32 * Y16S * 4);
        // ---- prefetch next yn tile into regs ----
        uint4 prh[2];
        if (nt < NTILES - 1) {
            const uint32_t* src = Yh + sd * NH + (((nt + 1) * TN + sc) >> 1);
            prh[0] = *(const uint4*)&src[0];
            prh[1] = *(const uint4*)&src[4];
        }

        // ---- per 16-col group: MMA1 -> h2-ex2 -> MMA2 (+ ones-B S MMA) ----
        #pragma unroll
        for (int nip = 0; nip < 2; nip++) {
            float c[2][2][4];                    // [ni][mi][q]
            #pragma unroll
            for (int i = 0; i < 2; i++)
                #pragma unroll
                for (int j = 0; j < 2; j++)
                    #pragma unroll
                    for (int q = 0; q < 4; q++) c[i][j][q] = 0.0f;
            uint32_t bq0[4], bq1[4];
            ldsm_x4_t(bq0, a1base + bufoff + (uint32_t)(nip * 32));
            ldsm_x4_t(bq1, a1base + bufoff + (uint32_t)(16 * Y16S * 4 + nip * 32));
            mma16h(c[0][0], a1h[0][0], bq0[0], bq0[1]);
            mma16h(c[0][1], a1h[1][0], bq0[0], bq0[1]);
            mma16h(c[1][0], a1h[0][0], bq0[2], bq0[3]);
            mma16h(c[1][1], a1h[1][0], bq0[2], bq0[3]);
            mma16h(c[0][0], a1h[0][1], bq1[0], bq1[1]);
            mma16h(c[0][1], a1h[1][1], bq1[0], bq1[1]);
            mma16h(c[1][0], a1h[0][1], bq1[2], bq1[3]);
            mma16h(c[1][1], a1h[1][1], bq1[2], bq1[3]);

            // packed exp: pack fp32 accums -> f16x2 -> ex2.approx.f16x2 = A-frag
            uint32_t af[2][4];
            #pragma unroll
            for (int mi = 0; mi < 2; mi++) {
                af[mi][0] = ex2h2(packh2(c[0][mi][0], c[0][mi][1]));   // rows g,   cols 0-7
                af[mi][1] = ex2h2(packh2(c[0][mi][2], c[0][mi][3]));   // rows 8+g, cols 0-7
                af[mi][2] = ex2h2(packh2(c[1][mi][0], c[1][mi][1]));   // rows g,   cols 8-15
                af[mi][3] = ex2h2(packh2(c[1][mi][2], c[1][mi][3]));   // rows 8+g, cols 8-15
            }
            // MMA2: k = these 16 n-cols; B-frags via non-trans ldmatrix
            uint32_t b2a[4], b2b[4];
            ldsm_x4(b2a, a2base + bufoff + (uint32_t)(nip * 32));
            ldsm_x4(b2b, a2base + bufoff + (uint32_t)(16 * Y16S * 4 + nip * 32));
            mma16h(z[0][0], af[0], b2a[0], b2a[1]);
            mma16h(z[1][0], af[1], b2a[0], b2a[1]);
            mma16h(z[0][1], af[0], b2a[2], b2a[3]);
            mma16h(z[1][1], af[1], b2a[2], b2a[3]);
            mma16h(z[0][2], af[0], b2b[0], b2b[1]);
            mma16h(z[1][2], af[1], b2b[0], b2b[1]);
            mma16h(z[0][3], af[0], b2b[2], b2b[3]);
            mma16h(z[1][3], af[1], b2b[2], b2b[3]);
            // S: ones-B MMA -> every accumulator column equals S[row]
            mma16h(z[0][4], af[0], H2_ONE, H2_ONE);
            mma16h(z[1][4], af[1], H2_ONE, H2_ONE);
        }

        // ---- publish next buffer ----
        if (nt < NTILES - 1) {
            uint32_t* dst = y16n + ((nt + 1) & 1) * (32 * Y16S) + sd * Y16S + (sc >> 1);
            *(uint4*)&dst[0] = prh[0];
            *(uint4*)&dst[4] = prh[1];
        }
        __syncthreads();
    }

    // loop-end __syncthreads() ordered all smem reads -> alias words 0.. as zst
    float* zst = sm;                       // [4 wn][64 m][32 d] = 8192 floats
    // S partials per wn slice: every k4 lane holds the same value; lane k4==0 writes
    if (k4 == 0) {
        #pragma unroll
        for (int mi = 0; mi < 2; mi++) {
            sst[wn * 64 + mr + mi * 16 + g]     = z[mi][4][0];
            sst[wn * 64 + mr + mi * 16 + g + 8] = z[mi][4][2];
        }
    }
    #pragma unroll
    for (int mi = 0; mi < 2; mi++)
        #pragma unroll
        for (int di = 0; di < 4; di++) {
            int row = mr + mi * 16 + g;
            int d   = di * 8 + 2 * k4;
            float2 lo, hi;
            lo.x = z[mi][di][0]; lo.y = z[mi][di][1];
            hi.x = z[mi][di][2]; hi.y = z[mi][di][3];
            *(float2*)&zst[wn * 2048 + row * 32 + d]       = lo;
            *(float2*)&zst[wn * 2048 + (row + 8) * 32 + d] = hi;
        }
    __syncthreads();

    // ---- final: sum 4 wn slices, normalize, blend, store (m-pair per thread) ----
    {
        const int mp = t & 31;             // m-pair id: local m = 2mp, 2mp+1
        const int d0 = (t >> 5) * 4;
        const int ml = 2 * mp;
        float S0 = sst[ml] + sst[64 + ml] + sst[128 + ml] + sst[192 + ml];
        float S1 = sst[ml + 1] + sst[64 + ml + 1] + sst[128 + ml + 1] + sst[192 + ml + 1];
        float inv0 = 0.5f / S0, inv1 = 0.5f / S1;
        #pragma unroll
        for (int dd = 0; dd < 4; dd++) {
            int d = d0 + dd;
            float z0 = zst[ml * 32 + d] + zst[2048 + ml * 32 + d] +
                       zst[4096 + ml * 32 + d] + zst[6144 + ml * 32 + d];
            float z1 = zst[(ml + 1) * 32 + d] + zst[2048 + (ml + 1) * 32 + d] +
                       zst[4096 + (ml + 1) * 32 + d] + zst[6144 + (ml + 1) * 32 + d];
            float2 f = unpackh2(Yh[d * NH + ((m0 + ml) >> 1)]);
            float o0 = z0 * inv0 + 0.5f * f.x;
            float o1 = z1 * inv1 + 0.5f * f.y;
            if (OUT16) {
                oh[b * (D_SZ * NH) + d * NH + ((m0 + ml) >> 1)] = packh2(o0, o1);
            } else {
                float* po = of + b * (D_SZ * N_SZ) + d * N_SZ + m0 + ml;
                po[0] = o0;
                po[1] = o1;
            }
        }
    }
}

extern "C" void kernel_launch(void* const* d_in, const int* in_sizes, int n_in,
                              void* d_out, int out_size) {
    const float* x = (const float*)d_in[0];
    float* out = (float*)d_out;
    uint32_t *x16, *ping, *pong;
    cudaGetSymbolAddress((void**)&x16, g_x16);
    cudaGetSymbolAddress((void**)&ping, g_ping);
    cudaGetSymbolAddress((void**)&pong, g_pong);
    cudaFuncSetAttribute(ms_iter_mma<true>,
                         cudaFuncAttributeMaxDynamicSharedMemorySize, SMEM_BYTES);
    cudaFuncSetAttribute(ms_iter_mma<false>,
                         cudaFuncAttributeMaxDynamicSharedMemorySize, SMEM_BYTES);
    dim3 grid(N_SZ / BM, B_SZ);
    cvt16<<<B_SZ * D_SZ * NH / (256 * 4), 256>>>(x, x16);        // x -> fp16
    ms_iter_mma<true><<<grid, THREADS, SMEM_BYTES>>>(x16, ping, nullptr);
    ms_iter_mma<true><<<grid, THREADS, SMEM_BYTES>>>(ping, pong, nullptr);
    ms_iter_mma<false><<<grid, THREADS, SMEM_BYTES>>>(pong, nullptr, out);
}

// round 16
// speedup vs baseline: 1.3415x; 1.0065x over previous
#include <cuda_runtime.h>
#include <cuda_fp16.h>
#include <cstdint>

#define B_SZ 4
#define D_SZ 32
#define N_SZ 4096
#define NH (N_SZ / 2)
#define BM 64                  // m-cols per CTA (2 CTAs/SM)
#define TN 128
#define NTILES (N_SZ / TN)
#define THREADS 256
#define YMQS 68                // ymq stride (u32)
#define Y16S 68                // y16n stride (u32); row stride 272B -> LDSM conflict-free
#define H2_ONE 0x3C003C00u     // fp16x2 (1.0, 1.0)

// fp16x2 buffers (n-paired): [b][d][n/2]
__device__ uint32_t g_x16[B_SZ * D_SZ * NH];
__device__ uint32_t g_ping[B_SZ * D_SZ * NH];
__device__ uint32_t g_pong[B_SZ * D_SZ * NH];

// smem u32-word offsets
#define OFF_YMQ 0                           // [16][68] = 1088 (fp16x2 C1*Ym, d-paired)
#define OFF_Y16N 1088                       // 2 x [32][68] = 4352 (fp16x2 yn, n-paired)
#define OFF_SS 8192                         // [4][64] (after zst region)
#define SMEM_WORDS 8448
#define SMEM_BYTES (SMEM_WORDS * 4)         // 33792

static __device__ __forceinline__ uint32_t smem_u32(const void* p) {
    uint32_t a;
    asm("{ .reg .u64 t; cvta.to.shared.u64 t, %1; cvt.u32.u64 %0, t; }" : "=r"(a) : "l"(p));
    return a;
}
static __device__ __forceinline__ uint32_t ex2h2(uint32_t x) {
    uint32_t r; asm("ex2.approx.f16x2 %0, %1;" : "=r"(r) : "r"(x)); return r;
}
static __device__ __forceinline__ uint32_t packh2(float lo, float hi) {
    __half2 h = __floats2half2_rn(lo, hi);
    return *reinterpret_cast<uint32_t*>(&h);
}
static __device__ __forceinline__ float2 unpackh2(uint32_t u) {
    return __half22float2(*reinterpret_cast<__half2*>(&u));
}
static __device__ __forceinline__ void ldsm_x4(uint32_t* r, uint32_t addr) {
    asm volatile("ldmatrix.sync.aligned.m8n8.x4.shared.b16 {%0,%1,%2,%3}, [%4];"
        : "=r"(r[0]), "=r"(r[1]), "=r"(r[2]), "=r"(r[3]) : "r"(addr));
}
static __device__ __forceinline__ void ldsm_x4_t(uint32_t* r, uint32_t addr) {
    asm volatile("ldmatrix.sync.aligned.m8n8.x4.trans.shared.b16 {%0,%1,%2,%3}, [%4];"
        : "=r"(r[0]), "=r"(r[1]), "=r"(r[2]), "=r"(r[3]) : "r"(addr));
}
static __device__ __forceinline__ void mma16h(float* c, const uint32_t* a,
                                              uint32_t b0, uint32_t b1) {
    asm("mma.sync.aligned.m16n8k16.row.col.f32.f16.f16.f32 "
        "{%0,%1,%2,%3},{%4,%5,%6,%7},{%8,%9},{%0,%1,%2,%3};"
        : "+f"(c[0]), "+f"(c[1]), "+f"(c[2]), "+f"(c[3])
        : "r"(a[0]), "r"(a[1]), "r"(a[2]), "r"(a[3]), "r"(b0), "r"(b1));
}

// fp32 -> fp16x2 pre-convert (whole input, once)
__global__ __launch_bounds__(256) void cvt16(const float* __restrict__ x,
                                             uint32_t* __restrict__ o) {
    int i = (blockIdx.x * 256 + threadIdx.x) * 4;   // u32 quad index
    float4 a = *(const float4*)&x[2 * i];
    float4 b = *(const float4*)&x[2 * i + 4];
    uint4 u = make_uint4(packh2(a.x, a.y), packh2(a.z, a.w),
                         packh2(b.x, b.y), packh2(b.z, b.w));
    *(uint4*)&o[i] = u;
}

// Mean-shift iteration, all-fp16 chain, PHASE-BATCHED tile body:
// [ldsm x4] [MMA1 x16: 8 independent 2-deep chains] [ex2 x8] [LDG prefetch]
// [MMA2 x20 incl ones-B S-MMAs]. Kt lives only in registers.
template <bool OUT16>
__global__ __launch_bounds__(THREADS, 2)
void ms_iter_mma(const uint32_t* __restrict__ xh, uint32_t* __restrict__ oh,
                 float* __restrict__ of) {
    extern __shared__ float sm[];
    uint32_t* smw  = reinterpret_cast<uint32_t*>(sm);
    uint32_t* ymq  = smw + OFF_YMQ;
    uint32_t* y16n = smw + OFF_Y16N;
    float*    sst  = sm + OFF_SS;

    const int b  = blockIdx.y;
    const int m0 = blockIdx.x * BM;
    const uint32_t* Yh = xh + b * (D_SZ * NH);

    const int t    = threadIdx.x;
    const int lane = t & 31;
    const int wid  = t >> 5;
    const int g    = lane >> 2;
    const int k4   = lane & 3;
    const int wm   = wid & 1;
    const int wn   = wid >> 1;
    const int mr   = wm * 32;
    const float C1 = 0.14426950408889634f;   // 0.1 * log2(e)

    // ldmatrix per-lane base addresses (bytes)
    const int mat = lane >> 3, rr = lane & 7;
    const uint32_t y16b = smem_u32(sm) + OFF_Y16N * 4;
    // MMA1 (.trans): mat = {d-octet lo/hi, n-col half}
    const uint32_t a1base = y16b + (uint32_t)((((mat & 1) * 8 + rr) * Y16S
                                               + 16 * wn + (mat >> 1) * 4) * 4);
    // MMA2 (non-trans): mat = {di-pair half, b0/b1}
    const uint32_t a2base = y16b + (uint32_t)((((mat >> 1) * 8 + rr) * Y16S
                                               + 16 * wn + (mat & 1) * 4) * 4);

    // staging ids: thread covers row sd, 16 pixels at sc
    const int sd = t >> 3;
    const int sc = (t & 7) * 16;

    // ---- stage ymq: [dpair r][m] = pack(C1*Y[2r][m], C1*Y[2r+1][m]) ----
    #pragma unroll
    for (int r2 = 0; r2 < 2; r2++) {
        int v = t + r2 * THREADS;                // 512 items
        int r = v >> 5, mm = (v & 31) * 2;
        float2 fa = unpackh2(Yh[(2 * r) * NH + ((m0 + mm) >> 1)]);
        float2 fb = unpackh2(Yh[(2 * r + 1) * NH + ((m0 + mm) >> 1)]);
        ymq[r * YMQS + mm]     = packh2(C1 * fa.x, C1 * fb.x);
        ymq[r * YMQS + mm + 1] = packh2(C1 * fa.y, C1 * fb.y);
    }
    // ---- stage y16n buf0 (pure copy) ----
    {
        const uint32_t* src = Yh + sd * NH + (sc >> 1);
        uint32_t* dst = y16n + sd * Y16S + (sc >> 1);
        *(uint4*)&dst[0] = *(const uint4*)&src[0];
        *(uint4*)&dst[4] = *(const uint4*)&src[4];
    }
    __syncthreads();

    // ---- hoist A1 frags (fp16, pre-scaled by C1): 32 Ym rows, 2 k16 chunks ----
    uint32_t a1h[2][2][4];
    #pragma unroll
    for (int mi = 0; mi < 2; mi++)
        #pragma unroll
        for (int kc = 0; kc < 2; kc++) {
            int row = mr + mi * 16 + g;
            a1h[mi][kc][0] = ymq[(8 * kc + k4) * YMQS + row];
            a1h[mi][kc][1] = ymq[(8 * kc + k4) * YMQS + row + 8];
            a1h[mi][kc][2] = ymq[(8 * kc + 4 + k4) * YMQS + row];
            a1h[mi][kc][3] = ymq[(8 * kc + 4 + k4) * YMQS + row + 8];
        }

    // z[mi][0..3] = Z data chunks; z[mi][4] = S (ones-B MMA)
    float z[2][5][4];
    #pragma unroll
    for (int i = 0; i < 2; i++)
        #pragma unroll
        for (int j = 0; j < 5; j++)
            #pragma unroll
            for (int q = 0; q < 4; q++) z[i][j][q] = 0.0f;

    for (int nt = 0; nt < NTILES; nt++) {
        const uint32_t bufoff = (uint32_t)(nt & 1) * (32 * Y16S * 4);

        // ---- phase 1: all MMA1 B-frags (4 independent ldsm) ----
        uint32_t bq[2][2][4];                // [nip][kc][frag]
        ldsm_x4_t(bq[0][0], a1base + bufoff);
        ldsm_x4_t(bq[0][1], a1base + bufoff + (uint32_t)(16 * Y16S * 4));
        ldsm_x4_t(bq[1][0], a1base + bufoff + 32u);
        ldsm_x4_t(bq[1][1], a1base + bufoff + (uint32_t)(16 * Y16S * 4 + 32));

        // ---- phase 2: all MMA1s (8 independent 2-deep chains) ----
        float c[2][2][2][4];                 // [nip][ni][mi][q]
        #pragma unroll
        for (int p = 0; p < 2; p++)
            #pragma unroll
            for (int i = 0; i < 2; i++)
                #pragma unroll
                for (int j = 0; j < 2; j++)
                    #pragma unroll
                    for (int q = 0; q < 4; q++) c[p][i][j][q] = 0.0f;
        #pragma unroll
        for (int p = 0; p < 2; p++)
            #pragma unroll
            for (int kc = 0; kc < 2; kc++) {
                mma16h(c[p][0][0], a1h[0][kc], bq[p][kc][0], bq[p][kc][1]);
                mma16h(c[p][0][1], a1h[1][kc], bq[p][kc][0], bq[p][kc][1]);
                mma16h(c[p][1][0], a1h[0][kc], bq[p][kc][2], bq[p][kc][3]);
                mma16h(c[p][1][1], a1h[1][kc], bq[p][kc][2], bq[p][kc][3]);
            }

        // ---- phase 3: all ex2 (8 independent) -> A-frags ----
        uint32_t af[2][2][4];                // [nip][mi][frag]
        #pragma unroll
        for (int p = 0; p < 2; p++)
            #pragma unroll
            for (int mi = 0; mi < 2; mi++) {
                af[p][mi][0] = ex2h2(packh2(c[p][0][mi][0], c[p][0][mi][1]));
                af[p][mi][1] = ex2h2(packh2(c[p][0][mi][2], c[p][0][mi][3]));
                af[p][mi][2] = ex2h2(packh2(c[p][1][mi][0], c[p][1][mi][1]));
                af[p][mi][3] = ex2h2(packh2(c[p][1][mi][2], c[p][1][mi][3]));
            }

        // ---- phase 4: LDG prefetch of next tile (low reg-pressure window) ----
        uint4 prh[2];
        if (nt < NTILES - 1) {
            const uint32_t* src = Yh + sd * NH + (((nt + 1) * TN + sc) >> 1);
            prh[0] = *(const uint4*)&src[0];
            prh[1] = *(const uint4*)&src[4];
        }

        // ---- phase 5: MMA2s (all independent accumulations) + S-MMAs ----
        #pragma unroll
        for (int p = 0; p < 2; p++) {
            uint32_t b2a[4], b2b[4];
            ldsm_x4(b2a, a2base + bufoff + (uint32_t)(p * 32));
            ldsm_x4(b2b, a2base + bufoff + (uint32_t)(16 * Y16S * 4 + p * 32));
            mma16h(z[0][0], af[p][0], b2a[0], b2a[1]);
            mma16h(z[1][0], af[p][1], b2a[0], b2a[1]);
            mma16h(z[0][1], af[p][0], b2a[2], b2a[3]);
            mma16h(z[1][1], af[p][1], b2a[2], b2a[3]);
            mma16h(z[0][2], af[p][0], b2b[0], b2b[1]);
            mma16h(z[1][2], af[p][1], b2b[0], b2b[1]);
            mma16h(z[0][3], af[p][0], b2b[2], b2b[3]);
            mma16h(z[1][3], af[p][1], b2b[2], b2b[3]);
            mma16h(z[0][4], af[p][0], H2_ONE, H2_ONE);
            mma16h(z[1][4], af[p][1], H2_ONE, H2_ONE);
        }

        // ---- publish next buffer ----
        if (nt < NTILES - 1) {
            uint32_t* dst = y16n + ((nt + 1) & 1) * (32 * Y16S) + sd * Y16S + (sc >> 1);
            *(uint4*)&dst[0] = prh[0];
            *(uint4*)&dst[4] = prh[1];
        }
        __syncthreads();
    }

    // loop-end __syncthreads() ordered all smem reads -> alias words 0.. as zst
    float* zst = sm;                       // [4 wn][64 m][32 d] = 8192 floats
    // S partials per wn slice: every k4 lane holds the same value; lane k4==0 writes
    if (k4 == 0) {
        #pragma unroll
        for (int mi = 0; mi < 2; mi++) {
            sst[wn * 64 + mr + mi * 16 + g]     = z[mi][4][0];
            sst[wn * 64 + mr + mi * 16 + g + 8] = z[mi][4][2];
        }
    }
    #pragma unroll
    for (int mi = 0; mi < 2; mi++)
        #pragma unroll
        for (int di = 0; di < 4; di++) {
            int row = mr + mi * 16 + g;
            int d   = di * 8 + 2 * k4;
            float2 lo, hi;
            lo.x = z[mi][di][0]; lo.y = z[mi][di][1];
            hi.x = z[mi][di][2]; hi.y = z[mi][di][3];
            *(float2*)&zst[wn * 2048 + row * 32 + d]       = lo;
            *(float2*)&zst[wn * 2048 + (row + 8) * 32 + d] = hi;
        }
    __syncthreads();

    // ---- final: sum 4 wn slices, normalize, blend, store (m-pair per thread) ----
    {
        const int mp = t & 31;             // m-pair id: local m = 2mp, 2mp+1
        const int d0 = (t >> 5) * 4;
        const int ml = 2 * mp;
        float S0 = sst[ml] + sst[64 + ml] + sst[128 + ml] + sst[192 + ml];
        float S1 = sst[ml + 1] + sst[64 + ml + 1] + sst[128 + ml + 1] + sst[192 + ml + 1];
        float inv0 = 0.5f / S0, inv1 = 0.5f / S1;
        #pragma unroll
        for (int dd = 0; dd < 4; dd++) {
            int d = d0 + dd;
            float z0 = zst[ml * 32 + d] + zst[2048 + ml * 32 + d] +
                       zst[4096 + ml * 32 + d] + zst[6144 + ml * 32 + d];
            float z1 = zst[(ml + 1) * 32 + d] + zst[2048 + (ml + 1) * 32 + d] +
                       zst[4096 + (ml + 1) * 32 + d] + zst[6144 + (ml + 1) * 32 + d];
            float2 f = unpackh2(Yh[d * NH + ((m0 + ml) >> 1)]);
            float o0 = z0 * inv0 + 0.5f * f.x;
            float o1 = z1 * inv1 + 0.5f * f.y;
            if (OUT16) {
                oh[b * (D_SZ * NH) + d * NH + ((m0 + ml) >> 1)] = packh2(o0, o1);
            } else {
                float* po = of + b * (D_SZ * N_SZ) + d * N_SZ + m0 + ml;
                po[0] = o0;
                po[1] = o1;
            }
        }
    }
}

extern "C" void kernel_launch(void* const* d_in, const int* in_sizes, int n_in,
                              void* d_out, int out_size) {
    const float* x = (const float*)d_in[0];
    float* out = (float*)d_out;
    uint32_t *x16, *ping, *pong;
    cudaGetSymbolAddress((void**)&x16, g_x16);
    cudaGetSymbolAddress((void**)&ping, g_ping);
    cudaGetSymbolAddress((void**)&pong, g_pong);
    cudaFuncSetAttribute(ms_iter_mma<true>,
                         cudaFuncAttributeMaxDynamicSharedMemorySize, SMEM_BYTES);
    cudaFuncSetAttribute(ms_iter_mma<false>,
                         cudaFuncAttributeMaxDynamicSharedMemorySize, SMEM_BYTES);
    dim3 grid(N_SZ / BM, B_SZ);
    cvt16<<<B_SZ * D_SZ * NH / (256 * 4), 256>>>(x, x16);        // x -> fp16
    ms_iter_mma<true><<<grid, THREADS, SMEM_BYTES>>>(x16, ping, nullptr);
    ms_iter_mma<true><<<grid, THREADS, SMEM_BYTES>>>(ping, pong, nullptr);
    ms_iter_mma<false><<<grid, THREADS, SMEM_BYTES>>>(pong, nullptr, out);
}